// round 6
// baseline (speedup 1.0000x reference)
#include <cuda_runtime.h>
#include <mma.h>
#include <math.h>
#include <stdint.h>

using namespace nvcuda;

#define HH 16
#define TT 2048
#define DQK 192
#define NOPEC 128
#define ROPEC 64
#define LORAC 512
#define VDIMC 128
#define SCALE_F 0.07216878364870323f   // 1/sqrt(192)

// Device scratch (no allocation allowed)
__device__ float g_Kn[HH * TT * NOPEC];   // per-head k_nope, tf32-rounded
__device__ float g_V [HH * TT * VDIMC];   // absorbed V_h = k_c @ w_uv[h], tf32-rounded
__device__ float g_rope[TT * ROPEC];      // k_pe, tf32-rounded (head-independent)

__device__ __forceinline__ float tf32r(float x) {
    uint32_t u;
    asm("cvt.rna.tf32.f32 %0, %1;" : "=r"(u) : "f"(x));
    return __uint_as_float(u);
}
__device__ __forceinline__ float4 tf32r4(float4 v) {
    return make_float4(tf32r(v.x), tf32r(v.y), tf32r(v.z), tf32r(v.w));
}

typedef wmma::fragment<wmma::matrix_a, 16, 16, 8, wmma::precision::tf32, wmma::row_major> FragA;
typedef wmma::fragment<wmma::matrix_b, 16, 16, 8, wmma::precision::tf32, wmma::row_major> FragBr;
typedef wmma::fragment<wmma::matrix_b, 16, 16, 8, wmma::precision::tf32, wmma::col_major> FragBc;
typedef wmma::fragment<wmma::accumulator, 16, 16, 8, float> FragC;

// ---------------------------------------------------------------------------
// Kernel 1: tensorized prep GEMM (unchanged from R5 — it passed at ~135us).
// ---------------------------------------------------------------------------
#define AS_LD 20
#define BS_LD 132

__global__ __launch_bounds__(256) void kv_gemm_wmma(
    const float* __restrict__ kc, const float* __restrict__ wkv, const float* __restrict__ wuv)
{
    const int m0 = blockIdx.x * 128, part = blockIdx.y, h = blockIdx.z;
    __shared__ float As[128 * AS_LD];
    __shared__ float Bs[16 * BS_LD];

    const int tid = threadIdx.x, wid = tid >> 5;
    const int wr = wid & 3, wc = wid >> 2;

    const float* Bsrc; int bstride;
    if (part == 0) { Bsrc = wkv + h * 256;             bstride = HH * 256; }
    else           { Bsrc = wuv + h * (LORAC * VDIMC); bstride = VDIMC;    }

    FragC acc[2][4];
    #pragma unroll
    for (int i = 0; i < 2; i++)
        #pragma unroll
        for (int j = 0; j < 4; j++) wmma::fill_fragment(acc[i][j], 0.f);

    for (int k0 = 0; k0 < LORAC; k0 += 16) {
        #pragma unroll
        for (int it = 0; it < 2; it++) {
            int i = tid + it * 256;
            int r = i >> 2, c4 = (i & 3) << 2;
            float4 v = tf32r4(*(const float4*)(kc + (size_t)(m0 + r) * LORAC + k0 + c4));
            *(float4*)&As[r * AS_LD + c4] = v;
        }
        #pragma unroll
        for (int it = 0; it < 2; it++) {
            int i = tid + it * 256;
            int k = i >> 5, n4 = (i & 31) << 2;
            float4 v = tf32r4(*(const float4*)(Bsrc + (size_t)(k0 + k) * bstride + n4));
            *(float4*)&Bs[k * BS_LD + n4] = v;
        }
        __syncthreads();

        #pragma unroll
        for (int ks = 0; ks < 2; ks++) {
            FragA a[2];
            FragBr b[4];
            #pragma unroll
            for (int i = 0; i < 2; i++)
                wmma::load_matrix_sync(a[i], As + (wr * 32 + 16 * i) * AS_LD + ks * 8, AS_LD);
            #pragma unroll
            for (int j = 0; j < 4; j++)
                wmma::load_matrix_sync(b[j], Bs + (ks * 8) * BS_LD + wc * 64 + 16 * j, BS_LD);
            #pragma unroll
            for (int i = 0; i < 2; i++)
                #pragma unroll
                for (int j = 0; j < 4; j++)
                    wmma::mma_sync(acc[i][j], a[i], b[j], acc[i][j]);
        }
        __syncthreads();
    }

    float* dst = (part == 0) ? (g_Kn + (size_t)h * TT * NOPEC) : (g_V + (size_t)h * TT * VDIMC);
    #pragma unroll
    for (int i = 0; i < 2; i++)
        #pragma unroll
        for (int j = 0; j < 4; j++) {
            #pragma unroll
            for (int e = 0; e < acc[i][j].num_elements; e++)
                acc[i][j].x[e] = tf32r(acc[i][j].x[e]);
            wmma::store_matrix_sync(dst + (size_t)(m0 + wr * 32 + 16 * i) * 128 + wc * 64 + 16 * j,
                                    acc[i][j], 128, wmma::mem_row_major);
        }
}

// Kernel 1b: pre-round rope once
__global__ void rope_round_kernel(const float* __restrict__ kpe)
{
    int i = blockIdx.x * blockDim.x + threadIdx.x;   // float4 over T*64
    if (i >= TT * ROPEC / 4) return;
    ((float4*)g_rope)[i] = tf32r4(((const float4*)kpe)[i]);
}

// ---------------------------------------------------------------------------
// Kernel 2: wmma-tf32 causal flash attention.
//   BM=128, BN=64, 256 thr, 8 warps (4 row-groups x 2 col-groups).
//   Warp tiles: S 32x32, O 32x64. No running max; O in accumulators.
// ---------------------------------------------------------------------------
#define QS_LD 200
#define KS_LD 200
#define VS_LD 132
#define PS_LD 68
#define SM_QS 0
#define SM_KS (SM_QS + 128 * QS_LD * 4)         // 102400
#define SM_VS (SM_KS + 64 * KS_LD * 4)          // +51200
#define SM_PS (SM_VS + 64 * VS_LD * 4)          // +33792
#define SM_LS (SM_PS + 128 * PS_LD * 4)         // +34816
#define FLASH_SMEM (SM_LS + 128 * 4)            // 222720 total

__global__ __launch_bounds__(256) void flash_wmma(
    const float* __restrict__ q, float* __restrict__ out)
{
    const int bid = blockIdx.x;
    const int h = bid & 15, idx = bid >> 4;
    const int qt = (idx & 1) ? (idx >> 1) : (15 - (idx >> 1));  // heavy/light interleave

    extern __shared__ char smem[];
    float* Qs = (float*)(smem + SM_QS);
    float* Ks = (float*)(smem + SM_KS);
    float* Vs = (float*)(smem + SM_VS);
    float* Ps = (float*)(smem + SM_PS);
    float* Ls = (float*)(smem + SM_LS);

    const int tid = threadIdx.x, wid = tid >> 5;
    const int wr = wid & 3, wc = wid >> 2;   // warp row group (x32), warp col group

    // Q tile 128x192, tf32-rounded
    #pragma unroll
    for (int it = 0; it < 24; it++) {
        int i = tid + it * 256;              // over 6144 float4
        int r = i / 48, c4 = (i % 48) * 4;
        float4 v = tf32r4(*(const float4*)(q + ((size_t)(qt * 128 + r) * HH + h) * DQK + c4));
        *(float4*)&Qs[r * QS_LD + c4] = v;
    }

    FragC oacc[2][4];
    #pragma unroll
    for (int i = 0; i < 2; i++)
        #pragma unroll
        for (int j = 0; j < 4; j++) wmma::fill_fragment(oacc[i][j], 0.f);

    const int srow = tid >> 1;               // softmax row owned by this thread (0..127)
    const int scg  = tid & 1;                // 32-col group
    float lsum = 0.f;

    const float* Knh = g_Kn + (size_t)h * TT * NOPEC;
    const float* Vh  = g_V  + (size_t)h * TT * VDIMC;
    const int njt = 2 * qt + 2;

    for (int jt = 0; jt < njt; jt++) {
        // ---- K tile 64x192: nope + rope (both pre-rounded) ----
        #pragma unroll
        for (int it = 0; it < 8; it++) {
            int i = tid + it * 256;          // 2048 float4
            int r = i >> 5, c4 = (i & 31) << 2;
            *(float4*)&Ks[r * KS_LD + c4] =
                *(const float4*)(Knh + (size_t)(jt * 64 + r) * NOPEC + c4);
        }
        #pragma unroll
        for (int it = 0; it < 4; it++) {
            int i = tid + it * 256;          // 1024 float4
            int r = i >> 4, c4 = (i & 15) << 2;
            *(float4*)&Ks[r * KS_LD + NOPEC + c4] =
                *(const float4*)(g_rope + (size_t)(jt * 64 + r) * ROPEC + c4);
        }
        // ---- V tile 64x128 (pre-rounded) ----
        #pragma unroll
        for (int it = 0; it < 8; it++) {
            int i = tid + it * 256;
            int r = i >> 5, c4 = (i & 31) << 2;
            *(float4*)&Vs[r * VS_LD + c4] =
                *(const float4*)(Vh + (size_t)(jt * 64 + r) * VDIMC + c4);
        }
        __syncthreads();

        // ---- S = Q @ K^T (warp: 32x32; 24 k-steps; 4 loads -> 4 mmas) ----
        {
            FragC sacc[2][2];
            #pragma unroll
            for (int i = 0; i < 2; i++)
                #pragma unroll
                for (int j = 0; j < 2; j++) wmma::fill_fragment(sacc[i][j], 0.f);
            #pragma unroll
            for (int ks = 0; ks < 24; ks++) {
                FragA a0, a1;
                FragBc b0, b1;
                wmma::load_matrix_sync(a0, Qs + (wr * 32) * QS_LD + ks * 8, QS_LD);
                wmma::load_matrix_sync(a1, Qs + (wr * 32 + 16) * QS_LD + ks * 8, QS_LD);
                wmma::load_matrix_sync(b0, Ks + (wc * 32) * KS_LD + ks * 8, KS_LD);
                wmma::load_matrix_sync(b1, Ks + (wc * 32 + 16) * KS_LD + ks * 8, KS_LD);
                wmma::mma_sync(sacc[0][0], a0, b0, sacc[0][0]);
                wmma::mma_sync(sacc[0][1], a0, b1, sacc[0][1]);
                wmma::mma_sync(sacc[1][0], a1, b0, sacc[1][0]);
                wmma::mma_sync(sacc[1][1], a1, b1, sacc[1][1]);
            }
            #pragma unroll
            for (int i = 0; i < 2; i++)
                #pragma unroll
                for (int j = 0; j < 2; j++)
                    wmma::store_matrix_sync(Ps + (wr * 32 + 16 * i) * PS_LD + wc * 32 + 16 * j,
                                            sacc[i][j], PS_LD, wmma::mem_row_major);
        }
        __syncthreads();

        // ---- softmax: p = exp(scale*s), causal mask, tf32-rounded ----
        {
            const int gr = qt * 128 + srow;
            const int jc0 = jt * 64 + scg * 32;
            float* prow = Ps + srow * PS_LD + scg * 32;
            #pragma unroll
            for (int c4 = 0; c4 < 32; c4 += 4) {
                float4 s = *(float4*)(prow + c4);
                int j = jc0 + c4;
                float p0 = (j     <= gr) ? tf32r(__expf(s.x * SCALE_F)) : 0.f;
                float p1 = (j + 1 <= gr) ? tf32r(__expf(s.y * SCALE_F)) : 0.f;
                float p2 = (j + 2 <= gr) ? tf32r(__expf(s.z * SCALE_F)) : 0.f;
                float p3 = (j + 3 <= gr) ? tf32r(__expf(s.w * SCALE_F)) : 0.f;
                lsum += (p0 + p1) + (p2 + p3);
                *(float4*)(prow + c4) = make_float4(p0, p1, p2, p3);
            }
        }
        __syncthreads();

        // ---- O += P @ V (warp: 32x64; 8 k-steps; 6 loads -> 8 mmas) ----
        #pragma unroll
        for (int ks = 0; ks < 8; ks++) {
            FragA a0, a1;
            wmma::load_matrix_sync(a0, Ps + (wr * 32) * PS_LD + ks * 8, PS_LD);
            wmma::load_matrix_sync(a1, Ps + (wr * 32 + 16) * PS_LD + ks * 8, PS_LD);
            #pragma unroll
            for (int j = 0; j < 4; j++) {
                FragBr b;
                wmma::load_matrix_sync(b, Vs + (ks * 8) * VS_LD + wc * 64 + 16 * j, VS_LD);
                wmma::mma_sync(oacc[0][j], a0, b, oacc[0][j]);
                wmma::mma_sync(oacc[1][j], a1, b, oacc[1][j]);
            }
        }
        __syncthreads();
    }

    // ---- row-sum reduce (2 threads per row) ----
    lsum += __shfl_xor_sync(0xffffffffu, lsum, 1);
    if (scg == 0) Ls[srow] = 1.f / lsum;

    // ---- stage O to smem (reuse Qs region, stride 132), normalize, store ----
    #pragma unroll
    for (int i = 0; i < 2; i++)
        #pragma unroll
        for (int j = 0; j < 4; j++)
            wmma::store_matrix_sync(Qs + (wr * 32 + 16 * i) * 132 + wc * 64 + 16 * j,
                                    oacc[i][j], 132, wmma::mem_row_major);
    __syncthreads();

    #pragma unroll
    for (int it = 0; it < 16; it++) {
        int i = tid + it * 256;                 // 4096 float4
        int r = i >> 5, c4 = (i & 31) << 2;
        float inv = Ls[r];
        float4 v = *(float4*)&Qs[r * 132 + c4];
        *(float4*)(out + (size_t)(qt * 128 + r) * (HH * VDIMC) + h * VDIMC + c4) =
            make_float4(v.x * inv, v.y * inv, v.z * inv, v.w * inv);
    }
}

// ---------------------------------------------------------------------------
extern "C" void kernel_launch(void* const* d_in, const int* in_sizes, int n_in,
                              void* d_out, int out_size)
{
    (void)in_sizes; (void)n_in; (void)out_size;
    const float* q   = (const float*)d_in[0];   // (T, H, 192)
    const float* kc  = (const float*)d_in[1];   // (T, 512)
    const float* kpe = (const float*)d_in[2];   // (T, 64)
    const float* wkv = (const float*)d_in[3];   // (512, 4096)
    const float* wuv = (const float*)d_in[4];   // (16, 512, 128)
    float* out = (float*)d_out;                 // (T, 2048)

    cudaFuncSetAttribute(flash_wmma, cudaFuncAttributeMaxDynamicSharedMemorySize, FLASH_SMEM);

    dim3 g1(TT / 128, 2, HH);
    kv_gemm_wmma<<<g1, 256>>>(kc, wkv, wuv);
    rope_round_kernel<<<(TT * ROPEC / 4 + 255) / 256, 256>>>(kpe);

    flash_wmma<<<(TT / 128) * HH, 256, FLASH_SMEM>>>(q, out);
}

// round 8
// speedup vs baseline: 1.5508x; 1.5508x over previous
#include <cuda_runtime.h>
#include <mma.h>
#include <math.h>
#include <stdint.h>

using namespace nvcuda;

#define HH 16
#define TT 2048
#define DQK 192
#define NOPEC 128
#define ROPEC 64
#define LORAC 512
#define VDIMC 128
#define SCALE_F 0.07216878364870323f   // 1/sqrt(192)

// Device scratch (no allocation allowed)
__device__ float g_Kn[HH * TT * NOPEC];   // per-head k_nope, tf32-rounded
__device__ float g_V [HH * TT * VDIMC];   // absorbed V_h, tf32-rounded
__device__ float g_rope[TT * ROPEC];      // k_pe, tf32-rounded

__device__ __forceinline__ float tf32r(float x) {
    uint32_t u;
    asm("cvt.rna.tf32.f32 %0, %1;" : "=r"(u) : "f"(x));
    return __uint_as_float(u);
}
__device__ __forceinline__ float4 tf32r4(float4 v) {
    return make_float4(tf32r(v.x), tf32r(v.y), tf32r(v.z), tf32r(v.w));
}

typedef wmma::fragment<wmma::matrix_a, 16, 16, 8, wmma::precision::tf32, wmma::row_major> FragA;
typedef wmma::fragment<wmma::matrix_b, 16, 16, 8, wmma::precision::tf32, wmma::row_major> FragBr;
typedef wmma::fragment<wmma::matrix_b, 16, 16, 8, wmma::precision::tf32, wmma::col_major> FragBc;
typedef wmma::fragment<wmma::accumulator, 16, 16, 8, float> FragC;

// ---------------------------------------------------------------------------
// Kernel 1: tensorized prep GEMM, BK=32.
// ---------------------------------------------------------------------------
#define AS_LD 36
#define BS_LD 132

__global__ __launch_bounds__(256) void kv_gemm_wmma(
    const float* __restrict__ kc, const float* __restrict__ wkv, const float* __restrict__ wuv)
{
    const int m0 = blockIdx.x * 128, part = blockIdx.y, h = blockIdx.z;
    __shared__ float As[128 * AS_LD];   // 128 x 32
    __shared__ float Bs[32 * BS_LD];    // 32 x 128

    const int tid = threadIdx.x, wid = tid >> 5;
    const int wr = wid & 3, wc = wid >> 2;

    const float* Bsrc; int bstride;
    if (part == 0) { Bsrc = wkv + h * 256;             bstride = HH * 256; }
    else           { Bsrc = wuv + h * (LORAC * VDIMC); bstride = VDIMC;    }

    FragC acc[2][4];
    #pragma unroll
    for (int i = 0; i < 2; i++)
        #pragma unroll
        for (int j = 0; j < 4; j++) wmma::fill_fragment(acc[i][j], 0.f);

    for (int k0 = 0; k0 < LORAC; k0 += 32) {
        #pragma unroll
        for (int it = 0; it < 4; it++) {
            int i = tid + it * 256;
            int r = i >> 3, c4 = (i & 7) << 2;
            float4 v = tf32r4(*(const float4*)(kc + (size_t)(m0 + r) * LORAC + k0 + c4));
            *(float4*)&As[r * AS_LD + c4] = v;
        }
        #pragma unroll
        for (int it = 0; it < 4; it++) {
            int i = tid + it * 256;
            int k = i >> 5, n4 = (i & 31) << 2;
            float4 v = tf32r4(*(const float4*)(Bsrc + (size_t)(k0 + k) * bstride + n4));
            *(float4*)&Bs[k * BS_LD + n4] = v;
        }
        __syncthreads();

        #pragma unroll
        for (int ks = 0; ks < 4; ks++) {
            FragA a[2];
            FragBr b[4];
            #pragma unroll
            for (int i = 0; i < 2; i++)
                wmma::load_matrix_sync(a[i], As + (wr * 32 + 16 * i) * AS_LD + ks * 8, AS_LD);
            #pragma unroll
            for (int j = 0; j < 4; j++)
                wmma::load_matrix_sync(b[j], Bs + (ks * 8) * BS_LD + wc * 64 + 16 * j, BS_LD);
            #pragma unroll
            for (int i = 0; i < 2; i++)
                #pragma unroll
                for (int j = 0; j < 4; j++)
                    wmma::mma_sync(acc[i][j], a[i], b[j], acc[i][j]);
        }
        __syncthreads();
    }

    float* dst = (part == 0) ? (g_Kn + (size_t)h * TT * NOPEC) : (g_V + (size_t)h * TT * VDIMC);
    #pragma unroll
    for (int i = 0; i < 2; i++)
        #pragma unroll
        for (int j = 0; j < 4; j++) {
            #pragma unroll
            for (int e = 0; e < acc[i][j].num_elements; e++)
                acc[i][j].x[e] = tf32r(acc[i][j].x[e]);
            wmma::store_matrix_sync(dst + (size_t)(m0 + wr * 32 + 16 * i) * 128 + wc * 64 + 16 * j,
                                    acc[i][j], 128, wmma::mem_row_major);
        }
}

// Kernel 1b: pre-round rope once
__global__ void rope_round_kernel(const float* __restrict__ kpe)
{
    int i = blockIdx.x * blockDim.x + threadIdx.x;
    if (i >= TT * ROPEC / 4) return;
    ((float4*)g_rope)[i] = tf32r4(((const float4*)kpe)[i]);
}

// ---------------------------------------------------------------------------
// Kernel 2: wmma-tf32 causal flash attention.
//   BM=BN=64, 256 thr, 8 warps (4x2). Q fragments preloaded in REGISTERS
//   (24 FragA/warp = 96 regs) -> no Qs smem; S-phase loads only K frags.
// ---------------------------------------------------------------------------
#define KS_LD 200
#define VS_LD 132
#define PS_LD 68
#define SM_KS 0
#define SM_VS (SM_KS + 64 * KS_LD * 4)          // 51200
#define SM_PS (SM_VS + 64 * VS_LD * 4)          // +33792
#define SM_LS (SM_PS + 64 * PS_LD * 4)          // +17408
#define FLASH_SMEM (SM_LS + 64 * 4)             // 102656 total

__global__ __launch_bounds__(256) void flash_wmma(
    const float* __restrict__ q, float* __restrict__ out)
{
    const int bid = blockIdx.x;
    const int h = bid & 15, idx = bid >> 4;
    const int qt = (idx & 1) ? (idx >> 1) : (31 - (idx >> 1));  // heavy/light interleave

    extern __shared__ char smem[];
    float* Ks = (float*)(smem + SM_KS);
    float* Vs = (float*)(smem + SM_VS);
    float* Ps = (float*)(smem + SM_PS);
    float* Ls = (float*)(smem + SM_LS);

    const int tid = threadIdx.x, wid = tid >> 5;
    const int wr = wid & 3, wc = wid >> 2;   // warp row (x16), warp col (x32)

    // ---- stage Q tile 64x192 into Ks, then preload per-warp A-frags ----
    #pragma unroll
    for (int it = 0; it < 12; it++) {
        int i = tid + it * 256;              // 3072 float4
        int r = i / 48, c4 = (i % 48) * 4;
        float4 v = tf32r4(*(const float4*)(q + ((size_t)(qt * 64 + r) * HH + h) * DQK + c4));
        *(float4*)&Ks[r * KS_LD + c4] = v;
    }
    __syncthreads();

    FragA aq[24];
    #pragma unroll
    for (int ks = 0; ks < 24; ks++)
        wmma::load_matrix_sync(aq[ks], Ks + (wr * 16) * KS_LD + ks * 8, KS_LD);
    __syncthreads();

    FragC oacc[4];
    #pragma unroll
    for (int j = 0; j < 4; j++) wmma::fill_fragment(oacc[j], 0.f);

    const int srow = tid >> 2;               // softmax row (0..63)
    const int scg  = tid & 3;                // 16-col group
    float lsum = 0.f;

    const float* Knh = g_Kn + (size_t)h * TT * NOPEC;
    const float* Vh  = g_V  + (size_t)h * TT * VDIMC;

    for (int jt = 0; jt <= qt; jt++) {
        // ---- K tile 64x192 (nope + pre-rounded rope) ----
        #pragma unroll
        for (int it = 0; it < 8; it++) {
            int i = tid + it * 256;
            int r = i >> 5, c4 = (i & 31) << 2;
            *(float4*)&Ks[r * KS_LD + c4] =
                *(const float4*)(Knh + (size_t)(jt * 64 + r) * NOPEC + c4);
        }
        #pragma unroll
        for (int it = 0; it < 4; it++) {
            int i = tid + it * 256;
            int r = i >> 4, c4 = (i & 15) << 2;
            *(float4*)&Ks[r * KS_LD + NOPEC + c4] =
                *(const float4*)(g_rope + (size_t)(jt * 64 + r) * ROPEC + c4);
        }
        // ---- V tile 64x128 ----
        #pragma unroll
        for (int it = 0; it < 8; it++) {
            int i = tid + it * 256;
            int r = i >> 5, c4 = (i & 31) << 2;
            *(float4*)&Vs[r * VS_LD + c4] =
                *(const float4*)(Vh + (size_t)(jt * 64 + r) * VDIMC + c4);
        }
        __syncthreads();

        // ---- S = Q @ K^T (warp 16x32; Q from regs, 2 loads -> 2 mmas) ----
        {
            FragC sacc[2];
            wmma::fill_fragment(sacc[0], 0.f);
            wmma::fill_fragment(sacc[1], 0.f);
            #pragma unroll
            for (int ks = 0; ks < 24; ks++) {
                FragBc b0, b1;
                wmma::load_matrix_sync(b0, Ks + (wc * 32) * KS_LD + ks * 8, KS_LD);
                wmma::load_matrix_sync(b1, Ks + (wc * 32 + 16) * KS_LD + ks * 8, KS_LD);
                wmma::mma_sync(sacc[0], aq[ks], b0, sacc[0]);
                wmma::mma_sync(sacc[1], aq[ks], b1, sacc[1]);
            }
            wmma::store_matrix_sync(Ps + (wr * 16) * PS_LD + wc * 32,      sacc[0], PS_LD, wmma::mem_row_major);
            wmma::store_matrix_sync(Ps + (wr * 16) * PS_LD + wc * 32 + 16, sacc[1], PS_LD, wmma::mem_row_major);
        }
        __syncthreads();

        // ---- softmax: p = exp(scale*s), causal mask, tf32-rounded ----
        {
            const int gr = qt * 64 + srow;
            const int jc0 = jt * 64 + scg * 16;
            float* prow = Ps + srow * PS_LD + scg * 16;
            #pragma unroll
            for (int c4 = 0; c4 < 16; c4 += 4) {
                float4 s = *(float4*)(prow + c4);
                int j = jc0 + c4;
                float p0 = (j     <= gr) ? tf32r(__expf(s.x * SCALE_F)) : 0.f;
                float p1 = (j + 1 <= gr) ? tf32r(__expf(s.y * SCALE_F)) : 0.f;
                float p2 = (j + 2 <= gr) ? tf32r(__expf(s.z * SCALE_F)) : 0.f;
                float p3 = (j + 3 <= gr) ? tf32r(__expf(s.w * SCALE_F)) : 0.f;
                lsum += (p0 + p1) + (p2 + p3);
                *(float4*)(prow + c4) = make_float4(p0, p1, p2, p3);
            }
        }
        __syncthreads();

        // ---- O += P @ V (warp 16x64; 8 k-steps) ----
        #pragma unroll
        for (int ks = 0; ks < 8; ks++) {
            FragA a;
            wmma::load_matrix_sync(a, Ps + (wr * 16) * PS_LD + ks * 8, PS_LD);
            #pragma unroll
            for (int j = 0; j < 4; j++) {
                FragBr b;
                wmma::load_matrix_sync(b, Vs + (ks * 8) * VS_LD + wc * 64 + 16 * j, VS_LD);
                wmma::mma_sync(oacc[j], a, b, oacc[j]);
            }
        }
        __syncthreads();
    }

    // ---- row-sum reduce (4 threads per row) ----
    lsum += __shfl_xor_sync(0xffffffffu, lsum, 1);
    lsum += __shfl_xor_sync(0xffffffffu, lsum, 2);
    if (scg == 0) Ls[srow] = 1.f / lsum;

    // ---- stage O to smem (reuse Vs), normalize, store ----
    #pragma unroll
    for (int j = 0; j < 4; j++)
        wmma::store_matrix_sync(Vs + (wr * 16) * VS_LD + wc * 64 + 16 * j,
                                oacc[j], VS_LD, wmma::mem_row_major);
    __syncthreads();

    #pragma unroll
    for (int it = 0; it < 8; it++) {
        int i = tid + it * 256;                 // 2048 float4
        int r = i >> 5, c4 = (i & 31) << 2;
        float inv = Ls[r];
        float4 v = *(float4*)&Vs[r * VS_LD + c4];
        *(float4*)(out + (size_t)(qt * 64 + r) * (HH * VDIMC) + h * VDIMC + c4) =
            make_float4(v.x * inv, v.y * inv, v.z * inv, v.w * inv);
    }
}

// ---------------------------------------------------------------------------
extern "C" void kernel_launch(void* const* d_in, const int* in_sizes, int n_in,
                              void* d_out, int out_size)
{
    (void)in_sizes; (void)n_in; (void)out_size;
    const float* q   = (const float*)d_in[0];   // (T, H, 192)
    const float* kc  = (const float*)d_in[1];   // (T, 512)
    const float* kpe = (const float*)d_in[2];   // (T, 64)
    const float* wkv = (const float*)d_in[3];   // (512, 4096)
    const float* wuv = (const float*)d_in[4];   // (16, 512, 128)
    float* out = (float*)d_out;                 // (T, 2048)

    cudaFuncSetAttribute(flash_wmma, cudaFuncAttributeMaxDynamicSharedMemorySize, FLASH_SMEM);

    dim3 g1(TT / 128, 2, HH);
    kv_gemm_wmma<<<g1, 256>>>(kc, wkv, wuv);
    rope_round_kernel<<<(TT * ROPEC / 4 + 255) / 256, 256>>>(kpe);

    flash_wmma<<<(TT / 64) * HH, 256, FLASH_SMEM>>>(q, out);
}

// round 9
// speedup vs baseline: 1.5876x; 1.0238x over previous
#include <cuda_runtime.h>
#include <mma.h>
#include <math.h>
#include <stdint.h>

using namespace nvcuda;

#define HH 16
#define TT 2048
#define DQK 192
#define NOPEC 128
#define ROPEC 64
#define LORAC 512
#define VDIMC 128
#define SCALE_F 0.07216878364870323f   // 1/sqrt(192)

// Device scratch (no allocation allowed)
__device__ float g_Kn[HH * TT * NOPEC];   // per-head k_nope, tf32-rounded
__device__ float g_V [HH * TT * VDIMC];   // absorbed V_h, tf32-rounded
__device__ float g_rope[TT * ROPEC];      // k_pe, tf32-rounded

__device__ __forceinline__ float tf32r(float x) {
    uint32_t u;
    asm("cvt.rna.tf32.f32 %0, %1;" : "=r"(u) : "f"(x));
    return __uint_as_float(u);
}
__device__ __forceinline__ float4 tf32r4(float4 v) {
    return make_float4(tf32r(v.x), tf32r(v.y), tf32r(v.z), tf32r(v.w));
}
__device__ __forceinline__ uint32_t smem_u32(const void* p) {
    uint32_t a;
    asm("{ .reg .u64 t; cvta.to.shared.u64 t, %1; cvt.u32.u64 %0, t; }" : "=r"(a) : "l"(p));
    return a;
}
#define CP_ASYNC16(saddr, gptr) \
    asm volatile("cp.async.cg.shared.global [%0], [%1], 16;" :: "r"(saddr), "l"(gptr))
#define CP_COMMIT() asm volatile("cp.async.commit_group;" ::: "memory")
#define CP_WAIT(n)  asm volatile("cp.async.wait_group %0;" :: "n"(n) : "memory")

typedef wmma::fragment<wmma::matrix_a, 16, 16, 8, wmma::precision::tf32, wmma::row_major> FragA;
typedef wmma::fragment<wmma::matrix_b, 16, 16, 8, wmma::precision::tf32, wmma::row_major> FragBr;
typedef wmma::fragment<wmma::matrix_b, 16, 16, 8, wmma::precision::tf32, wmma::col_major> FragBc;
typedef wmma::fragment<wmma::accumulator, 16, 16, 8, float> FragC;

// ---------------------------------------------------------------------------
// Kernel 1: tensorized prep GEMM, BK=32 (unchanged — 143.9us in R8).
// ---------------------------------------------------------------------------
#define AS_LD 36
#define BS_LD 132

__global__ __launch_bounds__(256) void kv_gemm_wmma(
    const float* __restrict__ kc, const float* __restrict__ wkv, const float* __restrict__ wuv)
{
    const int m0 = blockIdx.x * 128, part = blockIdx.y, h = blockIdx.z;
    __shared__ float As[128 * AS_LD];
    __shared__ float Bs[32 * BS_LD];

    const int tid = threadIdx.x, wid = tid >> 5;
    const int wr = wid & 3, wc = wid >> 2;

    const float* Bsrc; int bstride;
    if (part == 0) { Bsrc = wkv + h * 256;             bstride = HH * 256; }
    else           { Bsrc = wuv + h * (LORAC * VDIMC); bstride = VDIMC;    }

    FragC acc[2][4];
    #pragma unroll
    for (int i = 0; i < 2; i++)
        #pragma unroll
        for (int j = 0; j < 4; j++) wmma::fill_fragment(acc[i][j], 0.f);

    for (int k0 = 0; k0 < LORAC; k0 += 32) {
        #pragma unroll
        for (int it = 0; it < 4; it++) {
            int i = tid + it * 256;
            int r = i >> 3, c4 = (i & 7) << 2;
            float4 v = tf32r4(*(const float4*)(kc + (size_t)(m0 + r) * LORAC + k0 + c4));
            *(float4*)&As[r * AS_LD + c4] = v;
        }
        #pragma unroll
        for (int it = 0; it < 4; it++) {
            int i = tid + it * 256;
            int k = i >> 5, n4 = (i & 31) << 2;
            float4 v = tf32r4(*(const float4*)(Bsrc + (size_t)(k0 + k) * bstride + n4));
            *(float4*)&Bs[k * BS_LD + n4] = v;
        }
        __syncthreads();

        #pragma unroll
        for (int ks = 0; ks < 4; ks++) {
            FragA a[2];
            FragBr b[4];
            #pragma unroll
            for (int i = 0; i < 2; i++)
                wmma::load_matrix_sync(a[i], As + (wr * 32 + 16 * i) * AS_LD + ks * 8, AS_LD);
            #pragma unroll
            for (int j = 0; j < 4; j++)
                wmma::load_matrix_sync(b[j], Bs + (ks * 8) * BS_LD + wc * 64 + 16 * j, BS_LD);
            #pragma unroll
            for (int i = 0; i < 2; i++)
                #pragma unroll
                for (int j = 0; j < 4; j++)
                    wmma::mma_sync(acc[i][j], a[i], b[j], acc[i][j]);
        }
        __syncthreads();
    }

    float* dst = (part == 0) ? (g_Kn + (size_t)h * TT * NOPEC) : (g_V + (size_t)h * TT * VDIMC);
    #pragma unroll
    for (int i = 0; i < 2; i++)
        #pragma unroll
        for (int j = 0; j < 4; j++) {
            #pragma unroll
            for (int e = 0; e < acc[i][j].num_elements; e++)
                acc[i][j].x[e] = tf32r(acc[i][j].x[e]);
            wmma::store_matrix_sync(dst + (size_t)(m0 + wr * 32 + 16 * i) * 128 + wc * 64 + 16 * j,
                                    acc[i][j], 128, wmma::mem_row_major);
        }
}

// Kernel 1b: pre-round rope once
__global__ void rope_round_kernel(const float* __restrict__ kpe)
{
    int i = blockIdx.x * blockDim.x + threadIdx.x;
    if (i >= TT * ROPEC / 4) return;
    ((float4*)g_rope)[i] = tf32r4(((const float4*)kpe)[i]);
}

// ---------------------------------------------------------------------------
// Kernel 2: wmma-tf32 causal flash attention with cp.async double buffering.
//   BM=BN=64, 256 thr, 8 warps (4x2). Q frags in registers (24/warp).
//   K/V tiles double-buffered; tile jt+1 copies overlap tile jt compute.
// ---------------------------------------------------------------------------
#define KS_LD 200
#define VS_LD 132
#define PS_LD 68
#define KBYTES (64 * KS_LD * 4)                 // 51200
#define VBYTES (64 * VS_LD * 4)                 // 33792
#define SM_K0 0
#define SM_K1 KBYTES
#define SM_V0 (2 * KBYTES)
#define SM_V1 (2 * KBYTES + VBYTES)
#define SM_PS (2 * KBYTES + 2 * VBYTES)         // 169984
#define SM_LS (SM_PS + 64 * PS_LD * 4)          // +17408
#define FLASH_SMEM (SM_LS + 64 * 4)             // 187648 total

__device__ __forceinline__ void prefetch_tile(
    uint32_t sb, int buf, int jt, int tid,
    const float* __restrict__ Knh, const float* __restrict__ Vh)
{
    const uint32_t kb = sb + (buf ? SM_K1 : SM_K0);
    const uint32_t vb = sb + (buf ? SM_V1 : SM_V0);
    #pragma unroll
    for (int it = 0; it < 8; it++) {
        int i = tid + it * 256;                 // 2048 float4 (K nope)
        int r = i >> 5, c4 = (i & 31) << 2;
        CP_ASYNC16(kb + (uint32_t)(r * KS_LD + c4) * 4,
                   Knh + (size_t)(jt * 64 + r) * NOPEC + c4);
    }
    #pragma unroll
    for (int it = 0; it < 4; it++) {
        int i = tid + it * 256;                 // 1024 float4 (rope)
        int r = i >> 4, c4 = (i & 15) << 2;
        CP_ASYNC16(kb + (uint32_t)(r * KS_LD + NOPEC + c4) * 4,
                   g_rope + (size_t)(jt * 64 + r) * ROPEC + c4);
    }
    #pragma unroll
    for (int it = 0; it < 8; it++) {
        int i = tid + it * 256;                 // 2048 float4 (V)
        int r = i >> 5, c4 = (i & 31) << 2;
        CP_ASYNC16(vb + (uint32_t)(r * VS_LD + c4) * 4,
                   Vh + (size_t)(jt * 64 + r) * VDIMC + c4);
    }
    CP_COMMIT();
}

__global__ __launch_bounds__(256) void flash_wmma(
    const float* __restrict__ q, float* __restrict__ out)
{
    const int bid = blockIdx.x;
    const int h = bid & 15, idx = bid >> 4;
    const int qt = (idx & 1) ? (idx >> 1) : (31 - (idx >> 1));  // heavy/light interleave

    extern __shared__ char smem[];
    const uint32_t sb = smem_u32(smem);
    float* Ps = (float*)(smem + SM_PS);
    float* Ls = (float*)(smem + SM_LS);

    const int tid = threadIdx.x, wid = tid >> 5;
    const int wr = wid & 3, wc = wid >> 2;   // warp row (x16), warp col (x32)

    // ---- stage Q tile 64x192 into buffer K0, preload per-warp A-frags ----
    {
        float* Qstage = (float*)(smem + SM_K0);
        #pragma unroll
        for (int it = 0; it < 12; it++) {
            int i = tid + it * 256;              // 3072 float4
            int r = i / 48, c4 = (i % 48) * 4;
            float4 v = tf32r4(*(const float4*)(q + ((size_t)(qt * 64 + r) * HH + h) * DQK + c4));
            *(float4*)&Qstage[r * KS_LD + c4] = v;
        }
    }
    __syncthreads();

    FragA aq[24];
    #pragma unroll
    for (int ks = 0; ks < 24; ks++)
        wmma::load_matrix_sync(aq[ks], (float*)(smem + SM_K0) + (wr * 16) * KS_LD + ks * 8, KS_LD);
    __syncthreads();

    FragC oacc[4];
    #pragma unroll
    for (int j = 0; j < 4; j++) wmma::fill_fragment(oacc[j], 0.f);

    const int srow = tid >> 2;               // softmax row (0..63)
    const int scg  = tid & 3;                // 16-col group
    float lsum = 0.f;

    const float* Knh = g_Kn + (size_t)h * TT * NOPEC;
    const float* Vh  = g_V  + (size_t)h * TT * VDIMC;

    // prime the pipeline
    prefetch_tile(sb, 0, 0, tid, Knh, Vh);

    for (int jt = 0; jt <= qt; jt++) {
        // issue next tile's copies before waiting on this tile's
        if (jt < qt) {
            prefetch_tile(sb, (jt + 1) & 1, jt + 1, tid, Knh, Vh);
            CP_WAIT(1);
        } else {
            CP_WAIT(0);
        }
        __syncthreads();

        float* Ks = (float*)(smem + ((jt & 1) ? SM_K1 : SM_K0));
        float* Vs = (float*)(smem + ((jt & 1) ? SM_V1 : SM_V0));

        // ---- S = Q @ K^T (warp 16x32; Q from regs) ----
        {
            FragC sacc[2];
            wmma::fill_fragment(sacc[0], 0.f);
            wmma::fill_fragment(sacc[1], 0.f);
            #pragma unroll
            for (int ks = 0; ks < 24; ks++) {
                FragBc b0, b1;
                wmma::load_matrix_sync(b0, Ks + (wc * 32) * KS_LD + ks * 8, KS_LD);
                wmma::load_matrix_sync(b1, Ks + (wc * 32 + 16) * KS_LD + ks * 8, KS_LD);
                wmma::mma_sync(sacc[0], aq[ks], b0, sacc[0]);
                wmma::mma_sync(sacc[1], aq[ks], b1, sacc[1]);
            }
            wmma::store_matrix_sync(Ps + (wr * 16) * PS_LD + wc * 32,      sacc[0], PS_LD, wmma::mem_row_major);
            wmma::store_matrix_sync(Ps + (wr * 16) * PS_LD + wc * 32 + 16, sacc[1], PS_LD, wmma::mem_row_major);
        }
        __syncthreads();

        // ---- softmax: p = exp(scale*s), causal mask, tf32-rounded ----
        {
            const int gr = qt * 64 + srow;
            const int jc0 = jt * 64 + scg * 16;
            float* prow = Ps + srow * PS_LD + scg * 16;
            #pragma unroll
            for (int c4 = 0; c4 < 16; c4 += 4) {
                float4 s = *(float4*)(prow + c4);
                int j = jc0 + c4;
                float p0 = (j     <= gr) ? tf32r(__expf(s.x * SCALE_F)) : 0.f;
                float p1 = (j + 1 <= gr) ? tf32r(__expf(s.y * SCALE_F)) : 0.f;
                float p2 = (j + 2 <= gr) ? tf32r(__expf(s.z * SCALE_F)) : 0.f;
                float p3 = (j + 3 <= gr) ? tf32r(__expf(s.w * SCALE_F)) : 0.f;
                lsum += (p0 + p1) + (p2 + p3);
                *(float4*)(prow + c4) = make_float4(p0, p1, p2, p3);
            }
        }
        __syncthreads();

        // ---- O += P @ V (warp 16x64; 8 k-steps) ----
        #pragma unroll
        for (int ks = 0; ks < 8; ks++) {
            FragA a;
            wmma::load_matrix_sync(a, Ps + (wr * 16) * PS_LD + ks * 8, PS_LD);
            #pragma unroll
            for (int j = 0; j < 4; j++) {
                FragBr b;
                wmma::load_matrix_sync(b, Vs + (ks * 8) * VS_LD + wc * 64 + 16 * j, VS_LD);
                wmma::mma_sync(oacc[j], a, b, oacc[j]);
            }
        }
        __syncthreads();
    }

    // ---- row-sum reduce (4 threads per row) ----
    lsum += __shfl_xor_sync(0xffffffffu, lsum, 1);
    lsum += __shfl_xor_sync(0xffffffffu, lsum, 2);
    if (scg == 0) Ls[srow] = 1.f / lsum;

    // ---- stage O to smem (V0 buffer), normalize, store ----
    float* Os = (float*)(smem + SM_V0);
    #pragma unroll
    for (int j = 0; j < 4; j++)
        wmma::store_matrix_sync(Os + (wr * 16) * VS_LD + wc * 64 + 16 * j,
                                oacc[j], VS_LD, wmma::mem_row_major);
    __syncthreads();

    #pragma unroll
    for (int it = 0; it < 8; it++) {
        int i = tid + it * 256;                 // 2048 float4
        int r = i >> 5, c4 = (i & 31) << 2;
        float inv = Ls[r];
        float4 v = *(float4*)&Os[r * VS_LD + c4];
        *(float4*)(out + (size_t)(qt * 64 + r) * (HH * VDIMC) + h * VDIMC + c4) =
            make_float4(v.x * inv, v.y * inv, v.z * inv, v.w * inv);
    }
}

// ---------------------------------------------------------------------------
extern "C" void kernel_launch(void* const* d_in, const int* in_sizes, int n_in,
                              void* d_out, int out_size)
{
    (void)in_sizes; (void)n_in; (void)out_size;
    const float* q   = (const float*)d_in[0];   // (T, H, 192)
    const float* kc  = (const float*)d_in[1];   // (T, 512)
    const float* kpe = (const float*)d_in[2];   // (T, 64)
    const float* wkv = (const float*)d_in[3];   // (512, 4096)
    const float* wuv = (const float*)d_in[4];   // (16, 512, 128)
    float* out = (float*)d_out;                 // (T, 2048)

    cudaFuncSetAttribute(flash_wmma, cudaFuncAttributeMaxDynamicSharedMemorySize, FLASH_SMEM);

    dim3 g1(TT / 128, 2, HH);
    kv_gemm_wmma<<<g1, 256>>>(kc, wkv, wuv);
    rope_round_kernel<<<(TT * ROPEC / 4 + 255) / 256, 256>>>(kpe);

    flash_wmma<<<(TT / 64) * HH, 256, FLASH_SMEM>>>(q, out);
}